// round 2
// baseline (speedup 1.0000x reference)
#include <cuda_runtime.h>

// Problem constants (fixed shapes per reference)
#define NN 20000          // nodes
#define EE 320000         // raw edges
#define ET 340000         // edges incl. self loops
#define MAXF 256          // max feature width (h*c)

// ----------------------------------------------------------------------------
// Scratch (device globals; no allocation allowed)
// ----------------------------------------------------------------------------
__device__ float g_xl[NN * MAXF];
__device__ float g_xr[NN * MAXF];
__device__ float g_h0[NN * MAXF];
__device__ float g_h1[NN * MAXF];
__device__ float g_score[ET * 4];
__device__ int   g_deg[NN];
__device__ int   g_rowptr[NN + 1];
__device__ int   g_wr[NN];
__device__ int   g_colsrc[ET];
__device__ int   g_coleid[ET];

// ----------------------------------------------------------------------------
// CSR build: histogram -> scan -> scatter  (rebuilt every launch; cheap)
// ----------------------------------------------------------------------------
__global__ void zero_deg_kernel() {
    int i = blockIdx.x * blockDim.x + threadIdx.x;
    if (i < NN) g_deg[i] = 0;
}

__global__ void hist_kernel(const int* __restrict__ ei) {
    int e = blockIdx.x * blockDim.x + threadIdx.x;
    if (e >= ET) return;
    int dst = (e < EE) ? __ldg(ei + EE + e) : (e - EE);
    atomicAdd(&g_deg[dst], 1);
}

__global__ __launch_bounds__(1024) void scan_kernel() {
    __shared__ int sums[1024];
    const int t = threadIdx.x;
    constexpr int PER = (NN + 1023) / 1024;   // 20
    int base = t * PER;
    int local[PER];
    int s = 0;
    #pragma unroll
    for (int i = 0; i < PER; i++) {
        int v = (base + i < NN) ? g_deg[base + i] : 0;
        local[i] = s;
        s += v;
    }
    sums[t] = s;
    __syncthreads();
    for (int off = 1; off < 1024; off <<= 1) {
        int v = (t >= off) ? sums[t - off] : 0;
        __syncthreads();
        sums[t] += v;
        __syncthreads();
    }
    int offset = (t > 0) ? sums[t - 1] : 0;
    #pragma unroll
    for (int i = 0; i < PER; i++) {
        if (base + i < NN) {
            int r = offset + local[i];
            g_rowptr[base + i] = r;
            g_wr[base + i] = r;
        }
    }
    if (t == 1023) g_rowptr[NN] = sums[1023];
}

__global__ void scatter_kernel(const int* __restrict__ ei) {
    int e = blockIdx.x * blockDim.x + threadIdx.x;
    if (e >= ET) return;
    int src, dst;
    if (e < EE) { src = __ldg(ei + e); dst = __ldg(ei + EE + e); }
    else        { src = e - EE; dst = src; }
    int p = atomicAdd(&g_wr[dst], 1);
    g_colsrc[p] = src;
    g_coleid[p] = e;
}

// ----------------------------------------------------------------------------
// GEMM: C[n,m] = A[n,k] @ W[m,k]^T + bias[m]    (64x64 tile, 4x4 per thread)
// ----------------------------------------------------------------------------
__global__ __launch_bounds__(256)
void gemm_bias_kernel(const float* __restrict__ A, const float* __restrict__ W,
                      const float* __restrict__ bias, float* __restrict__ C,
                      int n, int m, int k)
{
    __shared__ float As[16][68];
    __shared__ float Ws[16][68];
    const int tx = threadIdx.x, ty = threadIdx.y;     // 16 x 16
    const int tid = ty * 16 + tx;
    const int rowBase = blockIdx.y * 64;
    const int colBase = blockIdx.x * 64;
    const int lr = tid >> 2;           // 0..63
    const int lk = (tid & 3) * 4;      // 0,4,8,12

    float acc[4][4];
    #pragma unroll
    for (int i = 0; i < 4; i++)
        #pragma unroll
        for (int j = 0; j < 4; j++) acc[i][j] = 0.f;

    for (int k0 = 0; k0 < k; k0 += 16) {
        float4 a = make_float4(0.f, 0.f, 0.f, 0.f);
        float4 w = make_float4(0.f, 0.f, 0.f, 0.f);
        if (rowBase + lr < n) a = *(const float4*)(A + (size_t)(rowBase + lr) * k + k0 + lk);
        if (colBase + lr < m) w = *(const float4*)(W + (size_t)(colBase + lr) * k + k0 + lk);
        As[lk + 0][lr] = a.x; As[lk + 1][lr] = a.y; As[lk + 2][lr] = a.z; As[lk + 3][lr] = a.w;
        Ws[lk + 0][lr] = w.x; Ws[lk + 1][lr] = w.y; Ws[lk + 2][lr] = w.z; Ws[lk + 3][lr] = w.w;
        __syncthreads();
        #pragma unroll
        for (int kk = 0; kk < 16; kk++) {
            float av[4], wv[4];
            #pragma unroll
            for (int i = 0; i < 4; i++) av[i] = As[kk][ty * 4 + i];
            #pragma unroll
            for (int j = 0; j < 4; j++) wv[j] = Ws[kk][tx * 4 + j];
            #pragma unroll
            for (int i = 0; i < 4; i++)
                #pragma unroll
                for (int j = 0; j < 4; j++)
                    acc[i][j] = fmaf(av[i], wv[j], acc[i][j]);
        }
        __syncthreads();
    }
    #pragma unroll
    for (int i = 0; i < 4; i++) {
        int row = rowBase + ty * 4 + i;
        if (row >= n) continue;
        #pragma unroll
        for (int j = 0; j < 4; j++) {
            int col = colBase + tx * 4 + j;
            if (col < m) C[(size_t)row * m + col] = acc[i][j] + bias[col];
        }
    }
}

// ----------------------------------------------------------------------------
// Edge scores: score[e,h] = sum_c leakyrelu(xl[src]+xr[dst]) * att[h,c]
// One thread per (edge, head).
// ----------------------------------------------------------------------------
__global__ __launch_bounds__(256)
void score_kernel(const float* __restrict__ xl, const float* __restrict__ xr,
                  const float* __restrict__ att, const int* __restrict__ ei,
                  float* __restrict__ score, int H, int C, int hc)
{
    int idx = blockIdx.x * blockDim.x + threadIdx.x;
    if (idx >= ET * H) return;
    int e = idx / H;
    int h = idx - e * H;
    int src, dst;
    if (e < EE) { src = __ldg(ei + e); dst = __ldg(ei + EE + e); }
    else        { src = e - EE; dst = src; }
    const float4* pl = (const float4*)(xl + (size_t)src * hc + h * C);
    const float4* pr = (const float4*)(xr + (size_t)dst * hc + h * C);
    const float4* pa = (const float4*)(att + h * C);
    float s = 0.f;
    int c4 = C >> 2;
    #pragma unroll 8
    for (int i = 0; i < c4; i++) {
        float4 a = pl[i], b = pr[i], t = pa[i];
        float m;
        m = a.x + b.x; m = m > 0.f ? m : 0.2f * m; s = fmaf(m, t.x, s);
        m = a.y + b.y; m = m > 0.f ? m : 0.2f * m; s = fmaf(m, t.y, s);
        m = a.z + b.z; m = m > 0.f ? m : 0.2f * m; s = fmaf(m, t.z, s);
        m = a.w + b.w; m = m > 0.f ? m : 0.2f * m; s = fmaf(m, t.w, s);
    }
    score[idx] = s;
}

// ----------------------------------------------------------------------------
// Per-destination softmax + aggregation + bias + relu.
// One 128-thread block per node. Warp w reduces head w (max, then den).
// Then chunked (32 edges) weighted gather, channel-parallel, coalesced.
// No float atomics anywhere.
// ----------------------------------------------------------------------------
__global__ __launch_bounds__(128)
void agg_kernel(const float* __restrict__ xl, const float* __restrict__ score,
                const int* __restrict__ rowptr, const int* __restrict__ colsrc,
                const int* __restrict__ coleid, const float* __restrict__ bias,
                float* __restrict__ out, int H, int C, int hc)
{
    int n = blockIdx.x;
    int tid = threadIdx.x;
    int lane = tid & 31, warp = tid >> 5;
    __shared__ float smax[4], sden[4];
    __shared__ float wsh[32 * 4];
    __shared__ int   ssrc[32];

    int r0 = rowptr[n], r1 = rowptr[n + 1];
    int deg = r1 - r0;

    if (warp < H) {
        int h = warp;
        float m = -3.402823466e38f;
        for (int i = lane; i < deg; i += 32)
            m = fmaxf(m, score[(size_t)coleid[r0 + i] * H + h]);
        #pragma unroll
        for (int o = 16; o; o >>= 1) m = fmaxf(m, __shfl_xor_sync(0xffffffffu, m, o));
        float d = 0.f;
        for (int i = lane; i < deg; i += 32)
            d += expf(score[(size_t)coleid[r0 + i] * H + h] - m);
        #pragma unroll
        for (int o = 16; o; o >>= 1) d += __shfl_xor_sync(0xffffffffu, d, o);
        if (lane == 0) { smax[h] = m; sden[h] = d + 1e-16f; }
    }
    __syncthreads();

    float acc0 = 0.f, acc1 = 0.f;
    int myh0 = tid / C;            // head of channel tid (valid iff tid < hc)
    int myh1 = (tid + 128) / C;    // head of channel tid+128 (iff hc > 128)

    for (int base = 0; base < deg; base += 32) {
        int cnt = min(32, deg - base);
        if (warp < H && lane < cnt) {
            int eid = coleid[r0 + base + lane];
            wsh[lane * H + warp] =
                expf(score[(size_t)eid * H + warp] - smax[warp]) / sden[warp];
            if (warp == 0) ssrc[lane] = colsrc[r0 + base + lane];
        }
        __syncthreads();
        #pragma unroll 4
        for (int i = 0; i < cnt; i++) {
            int src = ssrc[i];
            if (tid < hc)
                acc0 = fmaf(wsh[i * H + myh0], xl[(size_t)src * hc + tid], acc0);
            if (hc > 128)
                acc1 = fmaf(wsh[i * H + myh1], xl[(size_t)src * hc + tid + 128], acc1);
        }
        __syncthreads();
    }

    if (tid < hc)
        out[(size_t)n * hc + tid] = fmaxf(acc0 + bias[tid], 0.f);
    if (hc > 128) {
        int c2 = tid + 128;
        out[(size_t)n * hc + c2] = fmaxf(acc1 + bias[c2], 0.f);
    }
}

// ----------------------------------------------------------------------------
// Launch: 4 GATv2 layers. CSR built once per launch (deterministic work).
// ----------------------------------------------------------------------------
extern "C" void kernel_launch(void* const* d_in, const int* in_sizes, int n_in,
                              void* d_out, int out_size)
{
    const float* x  = (const float*)d_in[0];
    const int*   ei = (const int*)d_in[1];

    float *xl, *xr, *h0, *h1, *score;
    int *rowptr, *colsrc, *coleid;
    cudaGetSymbolAddress((void**)&xl, g_xl);
    cudaGetSymbolAddress((void**)&xr, g_xr);
    cudaGetSymbolAddress((void**)&h0, g_h0);
    cudaGetSymbolAddress((void**)&h1, g_h1);
    cudaGetSymbolAddress((void**)&score, g_score);
    cudaGetSymbolAddress((void**)&rowptr, g_rowptr);
    cudaGetSymbolAddress((void**)&colsrc, g_colsrc);
    cudaGetSymbolAddress((void**)&coleid, g_coleid);

    // CSR by destination
    zero_deg_kernel<<<(NN + 255) / 256, 256>>>();
    hist_kernel<<<(ET + 255) / 256, 256>>>(ei);
    scan_kernel<<<1, 1024>>>();
    scatter_kernel<<<(ET + 255) / 256, 256>>>(ei);

    struct LCfg { int din, H, C; };
    const LCfg cfg[4] = { {256, 4, 64}, {256, 4, 32}, {128, 4, 32}, {128, 1, 32} };
    float* outs[4] = { h0, h1, h0, (float*)d_out };

    const float* cur = x;
    for (int L = 0; L < 4; L++) {
        int din = cfg[L].din, H = cfg[L].H, C = cfg[L].C, hc = H * C;
        const float* Wl  = (const float*)d_in[2 + 6 * L + 0];
        const float* bl  = (const float*)d_in[2 + 6 * L + 1];
        const float* Wr  = (const float*)d_in[2 + 6 * L + 2];
        const float* br  = (const float*)d_in[2 + 6 * L + 3];
        const float* att = (const float*)d_in[2 + 6 * L + 4];
        const float* b   = (const float*)d_in[2 + 6 * L + 5];

        dim3 blk(16, 16);
        dim3 grd((hc + 63) / 64, (NN + 63) / 64);
        gemm_bias_kernel<<<grd, blk>>>(cur, Wl, bl, xl, NN, hc, din);
        gemm_bias_kernel<<<grd, blk>>>(cur, Wr, br, xr, NN, hc, din);

        int nth = ET * H;
        score_kernel<<<(nth + 255) / 256, 256>>>(xl, xr, att, ei, score, H, C, hc);

        agg_kernel<<<NN, 128>>>(xl, score, rowptr, colsrc, coleid, b, outs[L], H, C, hc);
        cur = outs[L];
    }
}

// round 4
// speedup vs baseline: 1.0245x; 1.0245x over previous
#include <cuda_runtime.h>
#include <cstdint>

// Problem constants (fixed shapes per reference)
#define NN 20000          // nodes
#define EE 320000         // raw edges
#define ET 340000         // edges incl. self loops
#define MAXF 256          // max feature width (h*c)

// ----------------------------------------------------------------------------
// Scratch (device globals; no allocation allowed)
// ----------------------------------------------------------------------------
__device__ float g_xl[NN * MAXF];
__device__ float g_xr[NN * MAXF];
__device__ float g_h0[NN * MAXF];
__device__ float g_h1[NN * MAXF];
__device__ float g_score[ET * 4];
__device__ int   g_deg[NN];
__device__ int   g_rowptr[NN + 1];
__device__ int   g_wr[NN];
__device__ int   g_colsrc[ET];
__device__ int   g_coleid[ET];

// ----------------------------------------------------------------------------
// CSR build: histogram -> scan -> scatter  (rebuilt every launch; cheap)
// ----------------------------------------------------------------------------
__global__ void zero_deg_kernel() {
    int i = blockIdx.x * blockDim.x + threadIdx.x;
    if (i < NN) g_deg[i] = 0;
}

__global__ void hist_kernel(const int* __restrict__ ei) {
    int e = blockIdx.x * blockDim.x + threadIdx.x;
    if (e >= ET) return;
    int dst = (e < EE) ? __ldg(ei + EE + e) : (e - EE);
    atomicAdd(&g_deg[dst], 1);
}

__global__ __launch_bounds__(1024) void scan_kernel() {
    __shared__ int sums[1024];
    const int t = threadIdx.x;
    constexpr int PER = (NN + 1023) / 1024;   // 20
    int base = t * PER;
    int local[PER];
    int s = 0;
    #pragma unroll
    for (int i = 0; i < PER; i++) {
        int v = (base + i < NN) ? g_deg[base + i] : 0;
        local[i] = s;
        s += v;
    }
    sums[t] = s;
    __syncthreads();
    for (int off = 1; off < 1024; off <<= 1) {
        int v = (t >= off) ? sums[t - off] : 0;
        __syncthreads();
        sums[t] += v;
        __syncthreads();
    }
    int offset = (t > 0) ? sums[t - 1] : 0;
    #pragma unroll
    for (int i = 0; i < PER; i++) {
        if (base + i < NN) {
            int r = offset + local[i];
            g_rowptr[base + i] = r;
            g_wr[base + i] = r;
        }
    }
    if (t == 1023) g_rowptr[NN] = sums[1023];
}

__global__ void scatter_kernel(const int* __restrict__ ei) {
    int e = blockIdx.x * blockDim.x + threadIdx.x;
    if (e >= ET) return;
    int src, dst;
    if (e < EE) { src = __ldg(ei + e); dst = __ldg(ei + EE + e); }
    else        { src = e - EE; dst = src; }
    int p = atomicAdd(&g_wr[dst], 1);
    g_colsrc[p] = src;
    g_coleid[p] = e;
}

// ----------------------------------------------------------------------------
// Tensor-core GEMM (3xTF32): C[n,m] = A[n,k] @ W[m,k]^T + bias[m]
// Block tile 64x64, 2x2 warps, each warp 32x32 via mma.m16n8k8.
// hi/lo tf32 split gives ~fp32 accuracy: d = ah*bh + ah*bl + al*bh.
// ----------------------------------------------------------------------------
__device__ __forceinline__ uint32_t f2tf32(float x) {
    uint32_t r;
    asm("cvt.rna.tf32.f32 %0, %1;" : "=r"(r) : "f"(x));
    return r;
}

__device__ __forceinline__ void mma_tf32(float* d, const uint32_t* a, const uint32_t* b) {
    asm volatile(
        "mma.sync.aligned.m16n8k8.row.col.f32.tf32.tf32.f32 "
        "{%0,%1,%2,%3}, {%4,%5,%6,%7}, {%8,%9}, {%0,%1,%2,%3};"
        : "+f"(d[0]), "+f"(d[1]), "+f"(d[2]), "+f"(d[3])
        : "r"(a[0]), "r"(a[1]), "r"(a[2]), "r"(a[3]), "r"(b[0]), "r"(b[1]));
}

__global__ __launch_bounds__(128)
void gemm_tf32_kernel(const float* __restrict__ A, const float* __restrict__ W,
                      const float* __restrict__ bias, float* __restrict__ C,
                      int n, int m, int k)
{
    __shared__ uint32_t Ah[64][36], Al[64][36], Wh[64][36], Wl[64][36];

    const int tid = threadIdx.x;
    const int warp = tid >> 5, lane = tid & 31;
    const int groupID = lane >> 2, quad = lane & 3;
    const int warpM = warp >> 1, warpN = warp & 1;
    const int rowBase = blockIdx.y * 64;
    const int colBase = blockIdx.x * 64;

    float acc[2][4][4];
    #pragma unroll
    for (int mt = 0; mt < 2; mt++)
        #pragma unroll
        for (int nt = 0; nt < 4; nt++)
            #pragma unroll
            for (int r = 0; r < 4; r++) acc[mt][nt][r] = 0.f;

    const int lr = tid >> 3;            // 0..15 (row within 16-row pass)
    const int lc = (tid & 7) * 4;       // 0,4,...,28

    for (int k0 = 0; k0 < k; k0 += 32) {
        // Load 64x32 A and 64x32 W tiles, split into tf32 hi/lo.
        #pragma unroll
        for (int p = 0; p < 4; p++) {
            int row = p * 16 + lr;
            float4 a = make_float4(0.f, 0.f, 0.f, 0.f);
            float4 w = make_float4(0.f, 0.f, 0.f, 0.f);
            if (rowBase + row < n)
                a = *(const float4*)(A + (size_t)(rowBase + row) * k + k0 + lc);
            if (colBase + row < m)
                w = *(const float4*)(W + (size_t)(colBase + row) * k + k0 + lc);
            float av[4] = {a.x, a.y, a.z, a.w};
            float wv[4] = {w.x, w.y, w.z, w.w};
            #pragma unroll
            for (int j = 0; j < 4; j++) {
                uint32_t ah = f2tf32(av[j]);
                Ah[row][lc + j] = ah;
                Al[row][lc + j] = f2tf32(av[j] - __uint_as_float(ah));
                uint32_t wh = f2tf32(wv[j]);
                Wh[row][lc + j] = wh;
                Wl[row][lc + j] = f2tf32(wv[j] - __uint_as_float(wh));
            }
        }
        __syncthreads();

        #pragma unroll
        for (int kk = 0; kk < 32; kk += 8) {
            uint32_t aH[2][4], aL[2][4], bH[4][2], bL[4][2];
            #pragma unroll
            for (int mt = 0; mt < 2; mt++) {
                int r0 = warpM * 32 + mt * 16 + groupID;
                aH[mt][0] = Ah[r0][kk + quad];
                aH[mt][1] = Ah[r0 + 8][kk + quad];
                aH[mt][2] = Ah[r0][kk + quad + 4];
                aH[mt][3] = Ah[r0 + 8][kk + quad + 4];
                aL[mt][0] = Al[r0][kk + quad];
                aL[mt][1] = Al[r0 + 8][kk + quad];
                aL[mt][2] = Al[r0][kk + quad + 4];
                aL[mt][3] = Al[r0 + 8][kk + quad + 4];
            }
            #pragma unroll
            for (int nt = 0; nt < 4; nt++) {
                int c0 = warpN * 32 + nt * 8 + groupID;
                bH[nt][0] = Wh[c0][kk + quad];
                bH[nt][1] = Wh[c0][kk + quad + 4];
                bL[nt][0] = Wl[c0][kk + quad];
                bL[nt][1] = Wl[c0][kk + quad + 4];
            }
            #pragma unroll
            for (int mt = 0; mt < 2; mt++)
                #pragma unroll
                for (int nt = 0; nt < 4; nt++) {
                    mma_tf32(acc[mt][nt], aL[mt], bH[nt]);
                    mma_tf32(acc[mt][nt], aH[mt], bL[nt]);
                    mma_tf32(acc[mt][nt], aH[mt], bH[nt]);
                }
        }
        __syncthreads();
    }

    // Epilogue: add bias, store (float2, cols are even-aligned).
    #pragma unroll
    for (int mt = 0; mt < 2; mt++) {
        int row0 = rowBase + warpM * 32 + mt * 16 + groupID;
        #pragma unroll
        for (int nt = 0; nt < 4; nt++) {
            int col = colBase + warpN * 32 + nt * 8 + quad * 2;
            if (col < m) {
                float b0 = bias[col], b1 = bias[col + 1];
                if (row0 < n) {
                    float2 v = make_float2(acc[mt][nt][0] + b0, acc[mt][nt][1] + b1);
                    *(float2*)(C + (size_t)row0 * m + col) = v;
                }
                if (row0 + 8 < n) {
                    float2 v = make_float2(acc[mt][nt][2] + b0, acc[mt][nt][3] + b1);
                    *(float2*)(C + (size_t)(row0 + 8) * m + col) = v;
                }
            }
        }
    }
}

// ----------------------------------------------------------------------------
// Edge scores: score[e,h] = sum_c leakyrelu(xl[src]+xr[dst]) * att[h,c]
// One thread per (edge, head).
// ----------------------------------------------------------------------------
__global__ __launch_bounds__(256)
void score_kernel(const float* __restrict__ xl, const float* __restrict__ xr,
                  const float* __restrict__ att, const int* __restrict__ ei,
                  float* __restrict__ score, int H, int C, int hc)
{
    int idx = blockIdx.x * blockDim.x + threadIdx.x;
    if (idx >= ET * H) return;
    int e = idx / H;
    int h = idx - e * H;
    int src, dst;
    if (e < EE) { src = __ldg(ei + e); dst = __ldg(ei + EE + e); }
    else        { src = e - EE; dst = src; }
    const float4* pl = (const float4*)(xl + (size_t)src * hc + h * C);
    const float4* pr = (const float4*)(xr + (size_t)dst * hc + h * C);
    const float4* pa = (const float4*)(att + h * C);
    float s = 0.f;
    int c4 = C >> 2;
    #pragma unroll 8
    for (int i = 0; i < c4; i++) {
        float4 a = pl[i], b = pr[i], t = pa[i];
        float m;
        m = a.x + b.x; m = m > 0.f ? m : 0.2f * m; s = fmaf(m, t.x, s);
        m = a.y + b.y; m = m > 0.f ? m : 0.2f * m; s = fmaf(m, t.y, s);
        m = a.z + b.z; m = m > 0.f ? m : 0.2f * m; s = fmaf(m, t.z, s);
        m = a.w + b.w; m = m > 0.f ? m : 0.2f * m; s = fmaf(m, t.w, s);
    }
    score[idx] = s;
}

// ----------------------------------------------------------------------------
// Per-destination softmax + aggregation + bias + relu.
// One 128-thread block per node. Warp w reduces head w (max, then den).
// Then chunked (32 edges) weighted gather, channel-parallel, coalesced.
// No float atomics anywhere.
// ----------------------------------------------------------------------------
__global__ __launch_bounds__(128)
void agg_kernel(const float* __restrict__ xl, const float* __restrict__ score,
                const int* __restrict__ rowptr, const int* __restrict__ colsrc,
                const int* __restrict__ coleid, const float* __restrict__ bias,
                float* __restrict__ out, int H, int C, int hc)
{
    int n = blockIdx.x;
    int tid = threadIdx.x;
    int lane = tid & 31, warp = tid >> 5;
    __shared__ float smax[4], sden[4];
    __shared__ float wsh[32 * 4];
    __shared__ int   ssrc[32];

    int r0 = rowptr[n], r1 = rowptr[n + 1];
    int deg = r1 - r0;

    if (warp < H) {
        int h = warp;
        float m = -3.402823466e38f;
        for (int i = lane; i < deg; i += 32)
            m = fmaxf(m, score[(size_t)coleid[r0 + i] * H + h]);
        #pragma unroll
        for (int o = 16; o; o >>= 1) m = fmaxf(m, __shfl_xor_sync(0xffffffffu, m, o));
        float d = 0.f;
        for (int i = lane; i < deg; i += 32)
            d += expf(score[(size_t)coleid[r0 + i] * H + h] - m);
        #pragma unroll
        for (int o = 16; o; o >>= 1) d += __shfl_xor_sync(0xffffffffu, d, o);
        if (lane == 0) { smax[h] = m; sden[h] = d + 1e-16f; }
    }
    __syncthreads();

    float acc0 = 0.f, acc1 = 0.f;
    int myh0 = tid / C;            // head of channel tid (valid iff tid < hc)
    int myh1 = (tid + 128) / C;    // head of channel tid+128 (iff hc > 128)

    for (int base = 0; base < deg; base += 32) {
        int cnt = min(32, deg - base);
        if (warp < H && lane < cnt) {
            int eid = coleid[r0 + base + lane];
            wsh[lane * H + warp] =
                expf(score[(size_t)eid * H + warp] - smax[warp]) / sden[warp];
            if (warp == 0) ssrc[lane] = colsrc[r0 + base + lane];
        }
        __syncthreads();
        #pragma unroll 4
        for (int i = 0; i < cnt; i++) {
            int src = ssrc[i];
            if (tid < hc)
                acc0 = fmaf(wsh[i * H + myh0], xl[(size_t)src * hc + tid], acc0);
            if (hc > 128)
                acc1 = fmaf(wsh[i * H + myh1], xl[(size_t)src * hc + tid + 128], acc1);
        }
        __syncthreads();
    }

    if (tid < hc)
        out[(size_t)n * hc + tid] = fmaxf(acc0 + bias[tid], 0.f);
    if (hc > 128) {
        int c2 = tid + 128;
        out[(size_t)n * hc + c2] = fmaxf(acc1 + bias[c2], 0.f);
    }
}

// ----------------------------------------------------------------------------
// Launch: 4 GATv2 layers. CSR built once per launch (deterministic work).
// ----------------------------------------------------------------------------
extern "C" void kernel_launch(void* const* d_in, const int* in_sizes, int n_in,
                              void* d_out, int out_size)
{
    const float* x  = (const float*)d_in[0];
    const int*   ei = (const int*)d_in[1];

    float *xl, *xr, *h0, *h1, *score;
    int *rowptr, *colsrc, *coleid;
    cudaGetSymbolAddress((void**)&xl, g_xl);
    cudaGetSymbolAddress((void**)&xr, g_xr);
    cudaGetSymbolAddress((void**)&h0, g_h0);
    cudaGetSymbolAddress((void**)&h1, g_h1);
    cudaGetSymbolAddress((void**)&score, g_score);
    cudaGetSymbolAddress((void**)&rowptr, g_rowptr);
    cudaGetSymbolAddress((void**)&colsrc, g_colsrc);
    cudaGetSymbolAddress((void**)&coleid, g_coleid);

    // CSR by destination
    zero_deg_kernel<<<(NN + 255) / 256, 256>>>();
    hist_kernel<<<(ET + 255) / 256, 256>>>(ei);
    scan_kernel<<<1, 1024>>>();
    scatter_kernel<<<(ET + 255) / 256, 256>>>(ei);

    struct LCfg { int din, H, C; };
    const LCfg cfg[4] = { {256, 4, 64}, {256, 4, 32}, {128, 4, 32}, {128, 1, 32} };
    float* outs[4] = { h0, h1, h0, (float*)d_out };

    const float* cur = x;
    for (int L = 0; L < 4; L++) {
        int din = cfg[L].din, H = cfg[L].H, C = cfg[L].C, hc = H * C;
        const float* Wl  = (const float*)d_in[2 + 6 * L + 0];
        const float* bl  = (const float*)d_in[2 + 6 * L + 1];
        const float* Wr  = (const float*)d_in[2 + 6 * L + 2];
        const float* br  = (const float*)d_in[2 + 6 * L + 3];
        const float* att = (const float*)d_in[2 + 6 * L + 4];
        const float* b   = (const float*)d_in[2 + 6 * L + 5];

        dim3 grd((hc + 63) / 64, (NN + 63) / 64);
        gemm_tf32_kernel<<<grd, 128>>>(cur, Wl, bl, xl, NN, hc, din);
        gemm_tf32_kernel<<<grd, 128>>>(cur, Wr, br, xr, NN, hc, din);

        int nth = ET * H;
        score_kernel<<<(nth + 255) / 256, 256>>>(xl, xr, att, ei, score, H, C, hc);

        agg_kernel<<<NN, 128>>>(xl, score, rowptr, colsrc, coleid, b, outs[L], H, C, hc);
        cur = outs[L];
    }
}

// round 5
// speedup vs baseline: 1.1473x; 1.1198x over previous
#include <cuda_runtime.h>
#include <cstdint>

// Problem constants (fixed shapes per reference)
#define NN 20000          // nodes
#define EE 320000         // raw edges
#define ET 340000         // edges incl. self loops
#define MAXF 256          // max feature width (h*c)

static constexpr int SMAX = 256;   // max edges whose scores live in SMEM

// ----------------------------------------------------------------------------
// Scratch (device globals; no allocation allowed)
// ----------------------------------------------------------------------------
__device__ float g_xl[NN * MAXF];
__device__ float g_xr[NN * MAXF];
__device__ float g_h0[NN * MAXF];
__device__ float g_h1[NN * MAXF];
__device__ int   g_deg[NN];
__device__ int   g_rowptr[NN + 1];
__device__ int   g_wr[NN];
__device__ int   g_colsrc[ET];

// ----------------------------------------------------------------------------
// CSR build: histogram -> scan -> scatter  (rebuilt every launch; cheap)
// ----------------------------------------------------------------------------
__global__ void zero_deg_kernel() {
    int i = blockIdx.x * blockDim.x + threadIdx.x;
    if (i < NN) g_deg[i] = 0;
}

__global__ void hist_kernel(const int* __restrict__ ei) {
    int e = blockIdx.x * blockDim.x + threadIdx.x;
    if (e >= ET) return;
    int dst = (e < EE) ? __ldg(ei + EE + e) : (e - EE);
    atomicAdd(&g_deg[dst], 1);
}

__global__ __launch_bounds__(1024) void scan_kernel() {
    __shared__ int sums[1024];
    const int t = threadIdx.x;
    constexpr int PER = (NN + 1023) / 1024;   // 20
    int base = t * PER;
    int local[PER];
    int s = 0;
    #pragma unroll
    for (int i = 0; i < PER; i++) {
        int v = (base + i < NN) ? g_deg[base + i] : 0;
        local[i] = s;
        s += v;
    }
    sums[t] = s;
    __syncthreads();
    for (int off = 1; off < 1024; off <<= 1) {
        int v = (t >= off) ? sums[t - off] : 0;
        __syncthreads();
        sums[t] += v;
        __syncthreads();
    }
    int offset = (t > 0) ? sums[t - 1] : 0;
    #pragma unroll
    for (int i = 0; i < PER; i++) {
        if (base + i < NN) {
            int r = offset + local[i];
            g_rowptr[base + i] = r;
            g_wr[base + i] = r;
        }
    }
    if (t == 1023) g_rowptr[NN] = sums[1023];
}

__global__ void scatter_kernel(const int* __restrict__ ei) {
    int e = blockIdx.x * blockDim.x + threadIdx.x;
    if (e >= ET) return;
    int src, dst;
    if (e < EE) { src = __ldg(ei + e); dst = __ldg(ei + EE + e); }
    else        { src = e - EE; dst = src; }
    int p = atomicAdd(&g_wr[dst], 1);
    g_colsrc[p] = src;
}

// ----------------------------------------------------------------------------
// Tensor-core GEMM (3xTF32): C[n,m] = A[n,k] @ W[m,k]^T + bias[m]
// ----------------------------------------------------------------------------
__device__ __forceinline__ uint32_t f2tf32(float x) {
    uint32_t r;
    asm("cvt.rna.tf32.f32 %0, %1;" : "=r"(r) : "f"(x));
    return r;
}

__device__ __forceinline__ void mma_tf32(float* d, const uint32_t* a, const uint32_t* b) {
    asm volatile(
        "mma.sync.aligned.m16n8k8.row.col.f32.tf32.tf32.f32 "
        "{%0,%1,%2,%3}, {%4,%5,%6,%7}, {%8,%9}, {%0,%1,%2,%3};"
        : "+f"(d[0]), "+f"(d[1]), "+f"(d[2]), "+f"(d[3])
        : "r"(a[0]), "r"(a[1]), "r"(a[2]), "r"(a[3]), "r"(b[0]), "r"(b[1]));
}

__global__ __launch_bounds__(128)
void gemm_tf32_kernel(const float* __restrict__ A, const float* __restrict__ W,
                      const float* __restrict__ bias, float* __restrict__ C,
                      int n, int m, int k)
{
    __shared__ uint32_t Ah[64][36], Al[64][36], Wh[64][36], Wl[64][36];

    const int tid = threadIdx.x;
    const int warp = tid >> 5, lane = tid & 31;
    const int groupID = lane >> 2, quad = lane & 3;
    const int warpM = warp >> 1, warpN = warp & 1;
    const int rowBase = blockIdx.y * 64;
    const int colBase = blockIdx.x * 64;

    float acc[2][4][4];
    #pragma unroll
    for (int mt = 0; mt < 2; mt++)
        #pragma unroll
        for (int nt = 0; nt < 4; nt++)
            #pragma unroll
            for (int r = 0; r < 4; r++) acc[mt][nt][r] = 0.f;

    const int lr = tid >> 3;
    const int lc = (tid & 7) * 4;

    for (int k0 = 0; k0 < k; k0 += 32) {
        #pragma unroll
        for (int p = 0; p < 4; p++) {
            int row = p * 16 + lr;
            float4 a = make_float4(0.f, 0.f, 0.f, 0.f);
            float4 w = make_float4(0.f, 0.f, 0.f, 0.f);
            if (rowBase + row < n)
                a = *(const float4*)(A + (size_t)(rowBase + row) * k + k0 + lc);
            if (colBase + row < m)
                w = *(const float4*)(W + (size_t)(colBase + row) * k + k0 + lc);
            float av[4] = {a.x, a.y, a.z, a.w};
            float wv[4] = {w.x, w.y, w.z, w.w};
            #pragma unroll
            for (int j = 0; j < 4; j++) {
                uint32_t ah = f2tf32(av[j]);
                Ah[row][lc + j] = ah;
                Al[row][lc + j] = f2tf32(av[j] - __uint_as_float(ah));
                uint32_t wh = f2tf32(wv[j]);
                Wh[row][lc + j] = wh;
                Wl[row][lc + j] = f2tf32(wv[j] - __uint_as_float(wh));
            }
        }
        __syncthreads();

        #pragma unroll
        for (int kk = 0; kk < 32; kk += 8) {
            uint32_t aH[2][4], aL[2][4], bH[4][2], bL[4][2];
            #pragma unroll
            for (int mt = 0; mt < 2; mt++) {
                int r0 = warpM * 32 + mt * 16 + groupID;
                aH[mt][0] = Ah[r0][kk + quad];
                aH[mt][1] = Ah[r0 + 8][kk + quad];
                aH[mt][2] = Ah[r0][kk + quad + 4];
                aH[mt][3] = Ah[r0 + 8][kk + quad + 4];
                aL[mt][0] = Al[r0][kk + quad];
                aL[mt][1] = Al[r0 + 8][kk + quad];
                aL[mt][2] = Al[r0][kk + quad + 4];
                aL[mt][3] = Al[r0 + 8][kk + quad + 4];
            }
            #pragma unroll
            for (int nt = 0; nt < 4; nt++) {
                int c0 = warpN * 32 + nt * 8 + groupID;
                bH[nt][0] = Wh[c0][kk + quad];
                bH[nt][1] = Wh[c0][kk + quad + 4];
                bL[nt][0] = Wl[c0][kk + quad];
                bL[nt][1] = Wl[c0][kk + quad + 4];
            }
            #pragma unroll
            for (int mt = 0; mt < 2; mt++)
                #pragma unroll
                for (int nt = 0; nt < 4; nt++) {
                    mma_tf32(acc[mt][nt], aL[mt], bH[nt]);
                    mma_tf32(acc[mt][nt], aH[mt], bL[nt]);
                    mma_tf32(acc[mt][nt], aH[mt], bH[nt]);
                }
        }
        __syncthreads();
    }

    #pragma unroll
    for (int mt = 0; mt < 2; mt++) {
        int row0 = rowBase + warpM * 32 + mt * 16 + groupID;
        #pragma unroll
        for (int nt = 0; nt < 4; nt++) {
            int col = colBase + warpN * 32 + nt * 8 + quad * 2;
            if (col < m) {
                float b0 = bias[col], b1 = bias[col + 1];
                if (row0 < n) {
                    float2 v = make_float2(acc[mt][nt][0] + b0, acc[mt][nt][1] + b1);
                    *(float2*)(C + (size_t)row0 * m + col) = v;
                }
                if (row0 + 8 < n) {
                    float2 v = make_float2(acc[mt][nt][2] + b0, acc[mt][nt][3] + b1);
                    *(float2*)(C + (size_t)(row0 + 8) * m + col) = v;
                }
            }
        }
    }
}

// ----------------------------------------------------------------------------
// Fused edge pipeline: per destination node, compute scores for all incoming
// edges (caching xl[src] rows in SMEM), softmax, weighted aggregation,
// bias + relu. One 128-thread block per node. No global score array,
// no coleid indirection, xl[src] read from GMEM exactly once per edge.
// ----------------------------------------------------------------------------
template<int H, int C>
__device__ __forceinline__ float slow_score(const float* __restrict__ xl, int src,
                                            const float* s_xr, const float* s_att, int h)
{
    // Correct fallback for edges beyond SMEM score capacity (never taken here).
    float s = 0.f;
    for (int c = 0; c < C; c++) {
        float v = xl[(size_t)src * (H * C) + h * C + c] + s_xr[h * C + c];
        v = v > 0.f ? v : 0.2f * v;
        s = fmaf(v, s_att[h * C + c], s);
    }
    return s;
}

template<int H, int C, int KC>
__global__ __launch_bounds__(128)
void fused_edge_kernel(const float* __restrict__ xl, const float* __restrict__ xr,
                       const float* __restrict__ att, const int* __restrict__ rowptr,
                       const int* __restrict__ colsrc, const float* __restrict__ bias,
                       float* __restrict__ out)
{
    constexpr int HC = H * C;
    __shared__ float s_xr[HC];
    __shared__ float s_att[HC];
    __shared__ float s_sc[SMAX * H];
    __shared__ float s_cache[KC * HC];
    __shared__ float s_max[H], s_den[H];

    const int n = blockIdx.x;
    const int tid = threadIdx.x;
    const int lane = tid & 31, warp = tid >> 5;

    const int r0 = rowptr[n], r1 = rowptr[n + 1];
    const int deg = r1 - r0;

    // Load xr[n] row and att into SMEM.
    for (int j = tid; j < HC; j += 128) {
        s_xr[j] = xr[(size_t)n * HC + j];
        s_att[j] = att[j];
    }
    __syncthreads();

    // Pass A: warp-per-edge score computation + xl row caching.
    for (int i = warp; i < deg; i += 4) {
        const int src = colsrc[r0 + i];
        const float* xrow = xl + (size_t)src * HC;
        #pragma unroll
        for (int h = 0; h < H; h++) {
            float p = 0.f;
            #pragma unroll
            for (int c = lane; c < C; c += 32) {
                float v = xrow[h * C + c];
                if (i < KC) s_cache[i * HC + h * C + c] = v;
                float m = v + s_xr[h * C + c];
                m = m > 0.f ? m : 0.2f * m;
                p = fmaf(m, s_att[h * C + c], p);
            }
            #pragma unroll
            for (int o = 16; o; o >>= 1) p += __shfl_xor_sync(0xffffffffu, p, o);
            if (lane == 0 && i < SMAX) s_sc[i * H + h] = p;
        }
    }
    __syncthreads();

    // Pass B: softmax over incoming edges, per head (warp h handles head h).
    if (warp < H) {
        const int h = warp;
        float m = -3.402823466e38f;
        for (int i = lane; i < deg; i += 32) {
            float s = (i < SMAX) ? s_sc[i * H + h]
                                 : slow_score<H, C>(xl, colsrc[r0 + i], s_xr, s_att, h);
            m = fmaxf(m, s);
        }
        #pragma unroll
        for (int o = 16; o; o >>= 1) m = fmaxf(m, __shfl_xor_sync(0xffffffffu, m, o));
        float d = 0.f;
        for (int i = lane; i < deg; i += 32) {
            float s = (i < SMAX) ? s_sc[i * H + h]
                                 : slow_score<H, C>(xl, colsrc[r0 + i], s_xr, s_att, h);
            d += expf(s - m);
        }
        #pragma unroll
        for (int o = 16; o; o >>= 1) d += __shfl_xor_sync(0xffffffffu, d, o);
        d += 1e-16f;
        float inv = 1.f / d;
        for (int i = lane; i < deg && i < SMAX; i += 32)
            s_sc[i * H + h] = expf(s_sc[i * H + h] - m) * inv;
        if (lane == 0) { s_max[h] = m; s_den[h] = d; }
    }
    __syncthreads();

    // Pass C: channel-parallel weighted aggregation (SMEM-resident hot path).
    float acc0 = 0.f, acc1 = 0.f;
    const int h0 = (tid < HC) ? tid / C : 0;
    const int h1 = (HC > 128) ? (tid + 128) / C : 0;

    int i = 0;
    // Hot path: everything in SMEM.
    int lim = deg < KC ? deg : KC;
    if (lim > SMAX) lim = SMAX;
    #pragma unroll 4
    for (; i < lim; i++) {
        if (tid < HC)
            acc0 = fmaf(s_sc[i * H + h0], s_cache[i * HC + tid], acc0);
        if (HC > 128)
            acc1 = fmaf(s_sc[i * H + h1], s_cache[i * HC + tid + 128], acc1);
    }
    // Overflow path: xl from GMEM, score from SMEM or recompute (rare/never).
    for (; i < deg; i++) {
        const int src = colsrc[r0 + i];
        float w0 = 0.f, w1 = 0.f;
        if (i < SMAX) {
            if (tid < HC) w0 = s_sc[i * H + h0];
            if (HC > 128) w1 = s_sc[i * H + h1];
        } else {
            if (tid < HC)
                w0 = expf(slow_score<H, C>(xl, src, s_xr, s_att, h0) - s_max[h0]) / s_den[h0];
            if (HC > 128)
                w1 = expf(slow_score<H, C>(xl, src, s_xr, s_att, h1) - s_max[h1]) / s_den[h1];
        }
        float v0 = 0.f, v1 = 0.f;
        if (i < KC) {
            if (tid < HC) v0 = s_cache[i * HC + tid];
            if (HC > 128) v1 = s_cache[i * HC + tid + 128];
        } else {
            if (tid < HC) v0 = xl[(size_t)src * HC + tid];
            if (HC > 128) v1 = xl[(size_t)src * HC + tid + 128];
        }
        acc0 = fmaf(w0, v0, acc0);
        acc1 = fmaf(w1, v1, acc1);
    }

    if (tid < HC)
        out[(size_t)n * HC + tid] = fmaxf(acc0 + bias[tid], 0.f);
    if (HC > 128) {
        int c2 = tid + 128;
        out[(size_t)n * HC + c2] = fmaxf(acc1 + bias[c2], 0.f);
    }
}

// ----------------------------------------------------------------------------
// Launch: 4 GATv2 layers. CSR built once per launch (deterministic work).
// ----------------------------------------------------------------------------
extern "C" void kernel_launch(void* const* d_in, const int* in_sizes, int n_in,
                              void* d_out, int out_size)
{
    const float* x  = (const float*)d_in[0];
    const int*   ei = (const int*)d_in[1];

    float *xl, *xr, *h0, *h1;
    int *rowptr, *colsrc;
    cudaGetSymbolAddress((void**)&xl, g_xl);
    cudaGetSymbolAddress((void**)&xr, g_xr);
    cudaGetSymbolAddress((void**)&h0, g_h0);
    cudaGetSymbolAddress((void**)&h1, g_h1);
    cudaGetSymbolAddress((void**)&rowptr, g_rowptr);
    cudaGetSymbolAddress((void**)&colsrc, g_colsrc);

    // CSR by destination
    zero_deg_kernel<<<(NN + 255) / 256, 256>>>();
    hist_kernel<<<(ET + 255) / 256, 256>>>(ei);
    scan_kernel<<<1, 1024>>>();
    scatter_kernel<<<(ET + 255) / 256, 256>>>(ei);

    struct LCfg { int din, H, C; };
    const LCfg cfg[4] = { {256, 4, 64}, {256, 4, 32}, {128, 4, 32}, {128, 1, 32} };
    float* outs[4] = { h0, h1, h0, (float*)d_out };

    const float* cur = x;
    for (int L = 0; L < 4; L++) {
        int din = cfg[L].din, H = cfg[L].H, C = cfg[L].C, hc = H * C;
        const float* Wl  = (const float*)d_in[2 + 6 * L + 0];
        const float* bl  = (const float*)d_in[2 + 6 * L + 1];
        const float* Wr  = (const float*)d_in[2 + 6 * L + 2];
        const float* br  = (const float*)d_in[2 + 6 * L + 3];
        const float* att = (const float*)d_in[2 + 6 * L + 4];
        const float* b   = (const float*)d_in[2 + 6 * L + 5];

        dim3 grd((hc + 63) / 64, (NN + 63) / 64);
        gemm_tf32_kernel<<<grd, 128>>>(cur, Wl, bl, xl, NN, hc, din);
        gemm_tf32_kernel<<<grd, 128>>>(cur, Wr, br, xr, NN, hc, din);

        switch (L) {
            case 0: fused_edge_kernel<4, 64, 32><<<NN, 128>>>(xl, xr, att, rowptr, colsrc, b, outs[L]); break;
            case 1: fused_edge_kernel<4, 32, 64><<<NN, 128>>>(xl, xr, att, rowptr, colsrc, b, outs[L]); break;
            case 2: fused_edge_kernel<4, 32, 64><<<NN, 128>>>(xl, xr, att, rowptr, colsrc, b, outs[L]); break;
            case 3: fused_edge_kernel<1, 32, 256><<<NN, 128>>>(xl, xr, att, rowptr, colsrc, b, outs[L]); break;
        }
        cur = outs[L];
    }
}